// round 14
// baseline (speedup 1.0000x reference)
#include <cuda_runtime.h>
#include <cuda_bf16.h>

// TenHotEncodeLayer: out[n, t, x[n,t,f]] = 1.0 for f in [0,10); all else 0.
// x: [32, 512, 10] int32, out: [32, 512, 5000] float32 (flat 81,920,000).
//
// Strategy v14 (= v13 with the grid constant fixed: 20,480,000 f4 / 5120
// = 4000, not 4096 — the off-grid CTAs were the illegal access).
// Kernel-internal dur is roofline-pinned (~46-48 us, 72-74% DRAM) across
// all structures; the measured total additionally pays launch/drain
// overhead that scales with CTA count (16384 CTAs: +2-3 us, 8000: ~+0).
// This variant halves the grid to 4000 CTAs, each owning an aligned
// 5120-float4 (20480 B = 160 L2-line) range, 20 x STG.128 per thread,
// plain stores. Range spans <= 6 rows -> npatch <= 60 candidates,
// prefetched before the fill, patched after the block barrier (L2-hot).

#define NUM_TOKENS 5000
#define NUM_F 10
#define TPB 256
#define CTA_F4 5120                    // 20480 B, 128B-aligned
#define CTA_ELEMS (CTA_F4 * 4)         // 20480 floats
#define ITERS (CTA_F4 / TPB)           // 20, exact
#define GRID 4000                      // 20,480,000 f4 / 5120 — exact cover

__global__ __launch_bounds__(TPB) void tenhot_kernel(
    const int* __restrict__ x, float4* __restrict__ out)
{
    const int blk = blockIdx.x;
    const int tid = threadIdx.x;

    // Flat element range owned by this CTA: [s, s + CTA_ELEMS)
    const long long s = (long long)blk * CTA_ELEMS;
    const int row_lo = (int)(s / NUM_TOKENS);
    const int row_hi = (int)((s + CTA_ELEMS - 1) / NUM_TOKENS);
    const int npatch = (row_hi - row_lo + 1) * NUM_F;   // <= 60

    // Prefetch scatter candidates before the fill (latency hidden).
    long long flat = -1;
    if (tid < npatch) {
        int r = row_lo + tid / NUM_F;
        int f = tid - (tid / NUM_F) * NUM_F;
        int c = __ldg(&x[r * NUM_F + f]);
        long long p = (long long)r * NUM_TOKENS + c;
        if (p >= s && p < s + CTA_ELEMS) flat = p;
    }

    // Aligned streaming fill: 20 x STG.128, each warp op = 4 full lines.
    float4* o = out + (size_t)blk * CTA_F4;
    const float4 z = make_float4(0.f, 0.f, 0.f, 0.f);
#pragma unroll
    for (int k = 0; k < ITERS; k++)
        o[tid + TPB * k] = z;

    __syncthreads();

    if (flat >= 0)
        reinterpret_cast<float*>(out)[flat] = 1.0f;
}

extern "C" void kernel_launch(void* const* d_in, const int* in_sizes, int n_in,
                              void* d_out, int out_size)
{
    const int* x = (const int*)d_in[0];
    float4* out = (float4*)d_out;
    tenhot_kernel<<<GRID, TPB>>>(x, out);
}

// round 15
// speedup vs baseline: 1.0773x; 1.0773x over previous
#include <cuda_runtime.h>
#include <cuda_bf16.h>

// TenHotEncodeLayer: out[n, t, x[n,t,f]] = 1.0 for f in [0,10); all else 0.
// x: [32, 512, 10] int32, out: [32, 512, 5000] float32 (flat 81,920,000 elems).
//
// FINAL — roofline- and grid-optimum-converged champion (best measured
// total: 47.46 us). Evidence from 14 rounds:
//   - 8+ structural variants (row/CTA granularities, bitmap single-pass,
//     memset+scatter, warp-per-row, persistent single-wave, barrier and
//     cache-op variants) all pin kernel dur at 46-48 us, 70-74% DRAM:
//     ~7.0 TB/s effective write rate (~87% of HBM3e spec) is the
//     streaming-write roofline for this op.
//   - Grid sweep (16384 / 8000 / 4000 / 2048 / 1184 CTAs) is unimodal with
//     the optimum at ~8000 CTAs x 10 KB: fewer CTAs lose drain-smoothing
//     (larger per-CTA fill spread), more CTAs pay launch/drain overhead.
// Structure: each CTA owns an aligned 2560-float4 (10240 B = 80 L2-line)
// range; 256 threads x 10 unrolled STG.128 (evict-first), no tail; the
// range intersects <= 3 rows (npatch <= 30 <= 256 scanning threads, and
// up to 4 rows near row boundaries is still < 256, covered by tid<npatch);
// candidates prefetched before the fill, patched with 1.0f after the block
// barrier while lines are L2-hot.

#define NUM_TOKENS 5000
#define NUM_F 10
#define TPB 256
#define CTA_F4 2560                    // 10240 B = 80 * 128B lines
#define CTA_ELEMS (CTA_F4 * 4)         // 10240 floats
#define ITERS (CTA_F4 / TPB)           // 10, exact
#define GRID 8000                      // 20,480,000 f4 / 2560 — exact cover

__global__ __launch_bounds__(TPB) void tenhot_kernel(
    const int* __restrict__ x, float4* __restrict__ out)
{
    const int blk = blockIdx.x;
    const int tid = threadIdx.x;

    // Flat element range owned by this CTA: [s, s + CTA_ELEMS)
    const long long s = (long long)blk * CTA_ELEMS;
    const int row_lo = (int)(s / NUM_TOKENS);
    const int row_hi = (int)((s + CTA_ELEMS - 1) / NUM_TOKENS);
    const int npatch = (row_hi - row_lo + 1) * NUM_F;   // <= 40

    // Prefetch scatter candidates before the fill (latency hidden).
    long long flat = -1;
    if (tid < npatch) {
        int r = row_lo + tid / NUM_F;
        int f = tid - (tid / NUM_F) * NUM_F;
        int c = __ldg(&x[r * NUM_F + f]);
        long long p = (long long)r * NUM_TOKENS + c;
        if (p >= s && p < s + CTA_ELEMS) flat = p;
    }

    // Aligned streaming fill: 10 x STG.128, each warp op = 4 full lines.
    float4* o = out + (size_t)blk * CTA_F4;
    const float4 z = make_float4(0.f, 0.f, 0.f, 0.f);
#pragma unroll
    for (int k = 0; k < ITERS; k++)
        __stcs(&o[tid + TPB * k], z);

    __syncthreads();

    if (flat >= 0)
        reinterpret_cast<float*>(out)[flat] = 1.0f;
}

extern "C" void kernel_launch(void* const* d_in, const int* in_sizes, int n_in,
                              void* d_out, int out_size)
{
    const int* x = (const int*)d_in[0];
    float4* out = (float4*)d_out;
    tenhot_kernel<<<GRID, TPB>>>(x, out);
}